// round 6
// baseline (speedup 1.0000x reference)
#include <cuda_runtime.h>

// out[b, q] = cos(x[b, q] + w[q]),  x: [4194304, 24] f32, w: [24] f32.
// THREADS=192 divisible by 6 => weight float4 index is loop-invariant
// (tid % 6). U=8 front-batched LDG.128 per thread; __cosf keeps the body
// tiny so regs stay ~40 (launch_bounds-capped) and occupancy holds at
// 48 warps/SM -> ~2x SM-level outstanding loads vs the U=4 variant.

#define THREADS 192
#define U 8

__global__ __launch_bounds__(THREADS, 8)
void qfl_cos_kernel(const float4* __restrict__ x,
                    const float4* __restrict__ w4,
                    float4* __restrict__ out,
                    int n4) {
    int tid  = threadIdx.x;
    int base = blockIdx.x * (THREADS * U) + tid;

    float4 W = __ldg(&w4[tid % 6]);   // loop-invariant broadcast

    if (base + (U - 1) * THREADS < n4) {
        float4 v[U];
#pragma unroll
        for (int k = 0; k < U; k++)
            v[k] = __ldcs(&x[base + k * THREADS]);

#pragma unroll
        for (int k = 0; k < U; k++) {
            float4 r;
            r.x = __cosf(v[k].x + W.x);
            r.y = __cosf(v[k].y + W.y);
            r.z = __cosf(v[k].z + W.z);
            r.w = __cosf(v[k].w + W.w);
            __stcs(&out[base + k * THREADS], r);
        }
    } else {
        // Tail (unused for the bench shape: 25165824 % 1536 == 0)
#pragma unroll
        for (int k = 0; k < U; k++) {
            int i = base + k * THREADS;
            if (i < n4) {
                float4 v = __ldcs(&x[i]);
                float4 r;
                r.x = __cosf(v.x + W.x);
                r.y = __cosf(v.y + W.y);
                r.z = __cosf(v.z + W.z);
                r.w = __cosf(v.w + W.w);
                __stcs(&out[i], r);
            }
        }
    }
}

extern "C" void kernel_launch(void* const* d_in, const int* in_sizes, int n_in,
                              void* d_out, int out_size) {
    const float* x = (const float*)d_in[0];
    const float* w = (const float*)d_in[1];
    float* out = (float*)d_out;

    int n  = in_sizes[0];   // 100663296
    int n4 = n >> 2;        // 25165824 = 16384 * 1536 (exact)

    int per_block = THREADS * U;     // 1536
    int blocks = (n4 + per_block - 1) / per_block;
    qfl_cos_kernel<<<blocks, THREADS>>>((const float4*)x, (const float4*)w,
                                        (float4*)out, n4);
}

// round 7
// speedup vs baseline: 1.0105x; 1.0105x over previous
#include <cuda_runtime.h>

// out[b, q] = cos(x[b, q] + w[q]),  x: [4194304, 24] f32, w: [24] f32.
// 256-bit path (sm_100+): each v8 (8 floats, 32B) lies inside one row
// (8 | 24); v8 index i uses weight octet (i % 3). THREADS=192 divisible
// by 3 and per-block stride divisible by 3 => octet index is the
// loop-invariant (tid % 3). One warp LDG.256 = 1024B contiguous -> longer
// same-row HBM bursts on read and write streams.

#define THREADS 192
#define U 2

__device__ __forceinline__ void ld_v8_cs(const float* p, float* v) {
    asm volatile("ld.global.cs.v8.f32 {%0,%1,%2,%3,%4,%5,%6,%7}, [%8];"
                 : "=f"(v[0]), "=f"(v[1]), "=f"(v[2]), "=f"(v[3]),
                   "=f"(v[4]), "=f"(v[5]), "=f"(v[6]), "=f"(v[7])
                 : "l"(p));
}

__device__ __forceinline__ void st_v8_cs(float* p, const float* v) {
    asm volatile("st.global.cs.v8.f32 [%0], {%1,%2,%3,%4,%5,%6,%7,%8};"
                 :: "l"(p),
                    "f"(v[0]), "f"(v[1]), "f"(v[2]), "f"(v[3]),
                    "f"(v[4]), "f"(v[5]), "f"(v[6]), "f"(v[7])
                 : "memory");
}

__global__ __launch_bounds__(THREADS, 8)
void qfl_cos_kernel(const float* __restrict__ x,
                    const float* __restrict__ w,
                    float* __restrict__ out,
                    int n8) {
    int tid   = threadIdx.x;
    int base8 = blockIdx.x * (THREADS * U) + tid;

    // Loop-invariant weight octet: w[(tid%3)*8 .. +8)
    const float* wp = w + (tid % 3) * 8;
    float W[8];
#pragma unroll
    for (int j = 0; j < 8; j++) W[j] = __ldg(wp + j);

    if (base8 + (U - 1) * THREADS < n8) {
        float v[U][8];
#pragma unroll
        for (int k = 0; k < U; k++)
            ld_v8_cs(x + (size_t)(base8 + k * THREADS) * 8, v[k]);

#pragma unroll
        for (int k = 0; k < U; k++) {
            float r[8];
#pragma unroll
            for (int j = 0; j < 8; j++)
                r[j] = __cosf(v[k][j] + W[j]);
            st_v8_cs(out + (size_t)(base8 + k * THREADS) * 8, r);
        }
    } else {
        // Tail (unused: n8 = 12582912 is divisible by THREADS*U = 384)
#pragma unroll
        for (int k = 0; k < U; k++) {
            int i = base8 + k * THREADS;
            if (i < n8) {
                float v[8], r[8];
                ld_v8_cs(x + (size_t)i * 8, v);
#pragma unroll
                for (int j = 0; j < 8; j++)
                    r[j] = __cosf(v[j] + W[j]);
                st_v8_cs(out + (size_t)i * 8, r);
            }
        }
    }
}

extern "C" void kernel_launch(void* const* d_in, const int* in_sizes, int n_in,
                              void* d_out, int out_size) {
    const float* x = (const float*)d_in[0];
    const float* w = (const float*)d_in[1];
    float* out = (float*)d_out;

    int n  = in_sizes[0];   // 100663296
    int n8 = n >> 3;        // 12582912 = 32768 * 384 (exact)

    int per_block = THREADS * U;     // 384
    int blocks = (n8 + per_block - 1) / per_block;
    qfl_cos_kernel<<<blocks, THREADS>>>(x, w, out, n8);
}